// round 4
// baseline (speedup 1.0000x reference)
#include <cuda_runtime.h>

#define IMG_H 480
#define IMG_W 640
#define NPIX (IMG_H * IMG_W)
#define NB 16

// Scratch: folded per-(dir,batch) transform [9 M + 3 c] and partial sums.
__device__ float  g_MC[2][NB * 12];
__device__ double g_sum[2];

// ---------------------------------------------------------------------------
// Precompute: M = K * Rd * Rs^T,  c = K*td - M*ts   for both directions.
// Also zeroes the accumulators (runs first on the stream every graph replay).
// ---------------------------------------------------------------------------
__global__ void pdsl_precompute(const float* __restrict__ R0,
                                const float* __restrict__ t0,
                                const float* __restrict__ R1,
                                const float* __restrict__ t1,
                                const float* __restrict__ K) {
    int t = threadIdx.x;
    if (t == 0) { g_sum[0] = 0.0; g_sum[1] = 0.0; }
    if (t >= 2 * NB) return;
    int dir = t / NB;
    int b   = t % NB;

    const float* Rs = (dir == 0 ? R0 : R1) + b * 9;
    const float* Rd = (dir == 0 ? R1 : R0) + b * 9;
    const float* ts = (dir == 0 ? t0 : t1) + b * 3;
    const float* td = (dir == 0 ? t1 : t0) + b * 3;

    // A = Rd * Rs^T
    float A[9];
#pragma unroll
    for (int i = 0; i < 3; i++)
#pragma unroll
        for (int j = 0; j < 3; j++)
            A[i * 3 + j] = Rd[i * 3 + 0] * Rs[j * 3 + 0]
                         + Rd[i * 3 + 1] * Rs[j * 3 + 1]
                         + Rd[i * 3 + 2] * Rs[j * 3 + 2];
    // M = K * A
    float M[9];
#pragma unroll
    for (int i = 0; i < 3; i++)
#pragma unroll
        for (int j = 0; j < 3; j++)
            M[i * 3 + j] = K[i * 3 + 0] * A[0 * 3 + j]
                         + K[i * 3 + 1] * A[1 * 3 + j]
                         + K[i * 3 + 2] * A[2 * 3 + j];

    float* mc = &g_MC[dir][b * 12];
#pragma unroll
    for (int i = 0; i < 9; i++) mc[i] = M[i];
#pragma unroll
    for (int i = 0; i < 3; i++) {
        float Ktd = K[i * 3 + 0] * td[0] + K[i * 3 + 1] * td[1] + K[i * 3 + 2] * td[2];
        mc[9 + i] = Ktd - (M[i * 3 + 0] * ts[0] + M[i * 3 + 1] * ts[1] + M[i * 3 + 2] * ts[2]);
    }
}

// ---------------------------------------------------------------------------
// Main: one thread per pixel, grid.y = direction, loop over 16 batches.
// ---------------------------------------------------------------------------
__global__ __launch_bounds__(256)
void pdsl_main(const float* __restrict__ depth0,
               const float* __restrict__ depth1,
               const float* __restrict__ ray) {
    const int dir = blockIdx.y;
    const float* __restrict__ dsrc = (dir == 0) ? depth0 : depth1;
    const float* __restrict__ ddst = (dir == 0) ? depth1 : depth0;

    __shared__ float sMC[NB * 12];
    const int tid = threadIdx.x;
    if (tid < NB * 12) sMC[tid] = g_MC[dir][tid];
    __syncthreads();

    const int p = blockIdx.x * blockDim.x + tid;
    float acc = 0.0f;

    if (p < NPIX) {
        const float rx = __ldg(&ray[3 * p + 0]);
        const float ry = __ldg(&ray[3 * p + 1]);
        const float rz = __ldg(&ray[3 * p + 2]);

        const float sx = (float)IMG_W / (float)(IMG_W - 1);
        const float sy = (float)IMG_H / (float)(IMG_H - 1);

#pragma unroll 4
        for (int b = 0; b < NB; b++) {
            const float* mc = &sMC[b * 12];
            float mrx = fmaf(mc[0], rx, fmaf(mc[1], ry, mc[2] * rz));
            float mry = fmaf(mc[3], rx, fmaf(mc[4], ry, mc[5] * rz));
            float mrz = fmaf(mc[6], rx, fmaf(mc[7], ry, mc[8] * rz));

            float d0 = __ldg(&dsrc[b * NPIX + p]);
            float u  = fmaf(d0, mrx, mc[9]);
            float v  = fmaf(d0, mry, mc[10]);
            float d  = fmaf(d0, mrz, mc[11]);

            float denom = fmaxf(d, 0.0f) + 1e-12f;
            float rcp;
            asm("rcp.approx.ftz.f32 %0, %1;" : "=f"(rcp) : "f"(denom));

            float x = fmaf(u * rcp, sx, -0.5f);
            float y = fmaf(v * rcp, sy, -0.5f);
            x = fminf(fmaxf(x, 0.0f), (float)(IMG_W - 1));
            y = fminf(fmaxf(y, 0.0f), (float)(IMG_H - 1));

            int x0 = (int)x;           // x >= 0 -> trunc == floor
            int y0 = (int)y;
            float wx = x - (float)x0;
            float wy = y - (float)y0;
            int x1 = min(x0 + 1, IMG_W - 1);
            int y1 = min(y0 + 1, IMG_H - 1);

            const float* plane = ddst + b * NPIX;
            int r0 = y0 * IMG_W;
            int r1 = y1 * IMG_W;
            float v00 = __ldg(&plane[r0 + x0]);
            float v01 = __ldg(&plane[r0 + x1]);
            float v10 = __ldg(&plane[r1 + x0]);
            float v11 = __ldg(&plane[r1 + x1]);

            float top = fmaf(wx, v01 - v00, v00);
            float bot = fmaf(wx, v11 - v10, v10);
            float s   = fmaf(wy, bot - top, top);

            acc += fabsf(d - s);
        }
    }

    // Block reduction -> atomicAdd to per-direction double accumulator.
#pragma unroll
    for (int off = 16; off > 0; off >>= 1)
        acc += __shfl_down_sync(0xffffffffu, acc, off);

    __shared__ float warpsum[8];
    if ((tid & 31) == 0) warpsum[tid >> 5] = acc;
    __syncthreads();
    if (tid < 8) {
        float s = warpsum[tid];
#pragma unroll
        for (int off = 4; off > 0; off >>= 1)
            s += __shfl_down_sync(0xffu, s, off);
        if (tid == 0) atomicAdd(&g_sum[dir], (double)s);
    }
}

__global__ void pdsl_finalize(float* __restrict__ out) {
    const double inv_n = 1.0 / (double)((long long)NB * NPIX);
    out[0] = (float)((g_sum[0] + g_sum[1]) * inv_n);
}

// ---------------------------------------------------------------------------
extern "C" void kernel_launch(void* const* d_in, const int* in_sizes, int n_in,
                              void* d_out, int out_size) {
    const float* depth0 = (const float*)d_in[0];
    const float* depth1 = (const float*)d_in[1];
    const float* R0     = (const float*)d_in[2];
    const float* t0     = (const float*)d_in[3];
    const float* R1     = (const float*)d_in[4];
    const float* t1     = (const float*)d_in[5];
    const float* K      = (const float*)d_in[6];
    const float* ray    = (const float*)d_in[7];

    pdsl_precompute<<<1, 32>>>(R0, t0, R1, t1, K);

    dim3 grid((NPIX + 255) / 256, 2);
    pdsl_main<<<grid, 256>>>(depth0, depth1, ray);

    pdsl_finalize<<<1, 1>>>((float*)d_out);
}